// round 3
// baseline (speedup 1.0000x reference)
#include <cuda_runtime.h>
#include <cstdint>

// ---------------- hash-grid constants (precomputed from reference config) ----
// L=16, D=2, BASE=16, DESIRED=2048, S = 2^(7/15), MAXP = 2^19
// scale_l = 16 * 2^(7l/15) - 1   (float32 cast of float64 value)
__constant__ float c_scale[16] = {
    15.0f,          21.1106061f,   29.5549331f,   41.2242532f,
    57.3502375f,    79.6349472f,  110.4304720f,  152.9872000f,
    211.7969070f,  293.0667790f,  405.3746690f,  560.5743900f,
    775.0469010f, 1071.4291820f, 1481.0036600f, 2047.0f
};
// RES+1 for the dense levels (RES = 16,23,31,43,59)
__constant__ uint32_t c_res1[5] = {17u, 24u, 32u, 44u, 60u};
// table offsets per level (cumsum of aligned sizes)
__constant__ int c_offset[16] = {
    0, 4920, 18744, 51512, 136696, 352696, 876984, 1401272,
    1925560, 2449848, 2974136, 3498424, 4022712, 4547000, 5071288, 5595576
};

#define NPTS 524288

// scratch (allocation-free rule: __device__ globals)
__device__ float g_feat[(size_t)NPTS * 32];
__device__ float g_h1[(size_t)NPTS * 256];
__device__ float g_h2[(size_t)NPTS * 256];

// ---------------------------------------------------------------- encode ----
__global__ void encode_kernel(const float* __restrict__ x,
                              const float* __restrict__ table,
                              float* __restrict__ feat, int N) {
    int i = blockIdx.x * blockDim.x + threadIdx.x;
    if (i >= N) return;

    float x0 = x[3 * i + 0] / 1.5f;
    float x1 = x[3 * i + 1] / 1.5f;
    float x2 = x[3 * i + 2] / 1.5f;

    #pragma unroll
    for (int l = 0; l < 16; l++) {
        float s = c_scale[l];
        float px = x0 * s + 0.5f;
        float py = x1 * s + 0.5f;
        float pz = x2 * s + 0.5f;
        float fx = floorf(px), fy = floorf(py), fz = floorf(pz);
        float tx = px - fx, ty = py - fy, tz = pz - fz;
        uint32_t X = (uint32_t)fx, Y = (uint32_t)fy, Z = (uint32_t)fz;
        float wx[2] = {1.0f - tx, tx};
        float wy[2] = {1.0f - ty, ty};
        float wz[2] = {1.0f - tz, tz};

        float a0 = 0.0f, a1 = 0.0f;
        #pragma unroll
        for (int c = 0; c < 8; c++) {
            uint32_t bx = (uint32_t)(c & 1);
            uint32_t by = (uint32_t)((c >> 1) & 1);
            uint32_t bz = (uint32_t)((c >> 2) & 1);
            uint32_t cx = X + bx, cy = Y + by, cz = Z + bz;
            uint32_t idx;
            if (l < 5) {
                uint32_t r1 = c_res1[l];
                idx = cx + cy * r1 + cz * r1 * r1;   // dense, always < size
            } else {
                idx = (cx * 1u ^ cy * 2654435761u ^ cz * 805459861u) & 524287u;
            }
            float w = wx[bx] * wy[by] * wz[bz];
            float2 t2 = __ldg((const float2*)table + (c_offset[l] + (int)idx));
            a0 += w * t2.x;
            a1 += w * t2.y;
        }
        feat[(size_t)i * 32 + 2 * l + 0] = a0;
        feat[(size_t)i * 32 + 2 * l + 1] = a1;
    }
}

// ------------------------------------------------- GEMM + bias + relu -------
// C[N,256] = relu(A[N,K] @ W[K,256] + b). BM=BN=128, BK=8, 256 thr, 8x8/thread.
__global__ void __launch_bounds__(256)
gemm_bias_relu(const float* __restrict__ A, const float* __restrict__ W,
               const float* __restrict__ bias, float* __restrict__ C,
               int N, int K) {
    __shared__ float As[8][128];
    __shared__ float Ws[8][128];

    const int tid = threadIdx.x;
    const int tx = tid & 15;   // 0..15 -> output col group
    const int ty = tid >> 4;   // 0..15 -> output row group
    const int rowBase = blockIdx.x * 128;
    const int colBase = blockIdx.y * 128;

    // A tile load mapping: one float4 / thread
    const int ar = tid >> 1;
    const int ak = (tid & 1) * 4;
    const int aRow = min(rowBase + ar, N - 1);
    // W tile load mapping: one float4 / thread
    const int wk = tid >> 5;
    const int wc = (tid & 31) * 4;

    float acc[8][8];
    #pragma unroll
    for (int i = 0; i < 8; i++)
        #pragma unroll
        for (int j = 0; j < 8; j++) acc[i][j] = 0.0f;

    for (int k0 = 0; k0 < K; k0 += 8) {
        float4 av = *(const float4*)(A + (size_t)aRow * K + k0 + ak);
        float4 wv = *(const float4*)(W + (size_t)(k0 + wk) * 256 + colBase + wc);
        __syncthreads();
        As[ak + 0][ar] = av.x;
        As[ak + 1][ar] = av.y;
        As[ak + 2][ar] = av.z;
        As[ak + 3][ar] = av.w;
        *(float4*)&Ws[wk][wc] = wv;
        __syncthreads();

        #pragma unroll
        for (int k = 0; k < 8; k++) {
            float a[8], b[8];
            *(float4*)&a[0] = *(const float4*)&As[k][ty * 8 + 0];
            *(float4*)&a[4] = *(const float4*)&As[k][ty * 8 + 4];
            *(float4*)&b[0] = *(const float4*)&Ws[k][tx * 8 + 0];
            *(float4*)&b[4] = *(const float4*)&Ws[k][tx * 8 + 4];
            #pragma unroll
            for (int i = 0; i < 8; i++)
                #pragma unroll
                for (int j = 0; j < 8; j++)
                    acc[i][j] += a[i] * b[j];
        }
    }

    float bj[8];
    #pragma unroll
    for (int j = 0; j < 8; j++) bj[j] = bias[colBase + tx * 8 + j];

    #pragma unroll
    for (int i = 0; i < 8; i++) {
        int row = rowBase + ty * 8 + i;
        if (row >= N) continue;
        float4 o0, o1;
        o0.x = fmaxf(acc[i][0] + bj[0], 0.0f);
        o0.y = fmaxf(acc[i][1] + bj[1], 0.0f);
        o0.z = fmaxf(acc[i][2] + bj[2], 0.0f);
        o0.w = fmaxf(acc[i][3] + bj[3], 0.0f);
        o1.x = fmaxf(acc[i][4] + bj[4], 0.0f);
        o1.y = fmaxf(acc[i][5] + bj[5], 0.0f);
        o1.z = fmaxf(acc[i][6] + bj[6], 0.0f);
        o1.w = fmaxf(acc[i][7] + bj[7], 0.0f);
        float* cp = C + (size_t)row * 256 + colBase + tx * 8;
        *(float4*)(cp + 0) = o0;
        *(float4*)(cp + 4) = o1;
    }
}

// ---------------------------------------------- final layer 256->3 + sigmoid
__global__ void final_kernel(const float* __restrict__ H,
                             const float* __restrict__ w4,
                             const float* __restrict__ b4,
                             float* __restrict__ out, int N) {
    __shared__ float ws[768];
    for (int t = threadIdx.x; t < 768; t += blockDim.x) ws[t] = w4[t];
    __syncthreads();

    int i = blockIdx.x * blockDim.x + threadIdx.x;
    if (i >= N) return;

    float a0 = b4[0], a1 = b4[1], a2 = b4[2];
    const float4* h4 = (const float4*)(H + (size_t)i * 256);
    #pragma unroll 8
    for (int q = 0; q < 64; q++) {
        float4 h = h4[q];
        int k = q * 4;
        a0 += h.x * ws[(k + 0) * 3 + 0];
        a1 += h.x * ws[(k + 0) * 3 + 1];
        a2 += h.x * ws[(k + 0) * 3 + 2];
        a0 += h.y * ws[(k + 1) * 3 + 0];
        a1 += h.y * ws[(k + 1) * 3 + 1];
        a2 += h.y * ws[(k + 1) * 3 + 2];
        a0 += h.z * ws[(k + 2) * 3 + 0];
        a1 += h.z * ws[(k + 2) * 3 + 1];
        a2 += h.z * ws[(k + 2) * 3 + 2];
        a0 += h.w * ws[(k + 3) * 3 + 0];
        a1 += h.w * ws[(k + 3) * 3 + 1];
        a2 += h.w * ws[(k + 3) * 3 + 2];
    }
    out[3 * i + 0] = 1.0f / (1.0f + expf(-a0));
    out[3 * i + 1] = 1.0f / (1.0f + expf(-a1));
    out[3 * i + 2] = 1.0f / (1.0f + expf(-a2));
}

// --------------------------------------------------------------- launcher ---
extern "C" void kernel_launch(void* const* d_in, const int* in_sizes, int n_in,
                              void* d_out, int out_size) {
    const float* x     = (const float*)d_in[0];
    const float* table = (const float*)d_in[1];
    const float* w1    = (const float*)d_in[2];
    const float* b1    = (const float*)d_in[3];
    const float* w2    = (const float*)d_in[4];
    const float* b2    = (const float*)d_in[5];
    const float* w3    = (const float*)d_in[6];
    const float* b3    = (const float*)d_in[7];
    const float* w4    = (const float*)d_in[8];
    const float* b4    = (const float*)d_in[9];
    float* out = (float*)d_out;

    int N = in_sizes[0] / 3;

    float *feat, *h1, *h2;
    cudaGetSymbolAddress((void**)&feat, g_feat);
    cudaGetSymbolAddress((void**)&h1, g_h1);
    cudaGetSymbolAddress((void**)&h2, g_h2);

    encode_kernel<<<(N + 255) / 256, 256>>>(x, table, feat, N);

    dim3 grid((N + 127) / 128, 2);
    gemm_bias_relu<<<grid, 256>>>(feat, w1, b1, h1, N, 32);
    gemm_bias_relu<<<grid, 256>>>(h1, w2, b2, h2, N, 256);
    gemm_bias_relu<<<grid, 256>>>(h2, w3, b3, h1, N, 256);

    final_kernel<<<(N + 255) / 256, 256>>>(h1, w4, b4, out, N);
}

// round 4
// speedup vs baseline: 7.7381x; 7.7381x over previous
#include <cuda_runtime.h>
#include <cuda_bf16.h>
#include <cstdint>

// ---------------- hash-grid constants (precomputed from reference config) ----
__constant__ float c_scale[16] = {
    15.0f,          21.1106061f,   29.5549331f,   41.2242532f,
    57.3502375f,    79.6349472f,  110.4304720f,  152.9872000f,
    211.7969070f,  293.0667790f,  405.3746690f,  560.5743900f,
    775.0469010f, 1071.4291820f, 1481.0036600f, 2047.0f
};
__constant__ uint32_t c_res1[5] = {17u, 24u, 32u, 44u, 60u};
__constant__ int c_offset[16] = {
    0, 4920, 18744, 51512, 136696, 352696, 876984, 1401272,
    1925560, 2449848, 2974136, 3498424, 4022712, 4547000, 5071288, 5595576
};

#define NPTS 524288

// scratch (allocation-free rule: __device__ globals)
__device__ __nv_bfloat16 g_featb[(size_t)NPTS * 32];
__device__ __nv_bfloat16 g_w1b[32 * 256];
__device__ __nv_bfloat16 g_w2b[256 * 256];
__device__ __nv_bfloat16 g_w3b[256 * 256];

// ------------------------------------------------------- weight conversion --
__global__ void cvtw_kernel(const float* __restrict__ w1,
                            const float* __restrict__ w2,
                            const float* __restrict__ w3,
                            __nv_bfloat16* __restrict__ o1,
                            __nv_bfloat16* __restrict__ o2,
                            __nv_bfloat16* __restrict__ o3) {
    int i = blockIdx.x * 256 + threadIdx.x;   // grid covers 65536
    if (i < 32 * 256) o1[i] = __float2bfloat16(w1[i]);
    o2[i] = __float2bfloat16(w2[i]);
    o3[i] = __float2bfloat16(w3[i]);
}

// ---------------------------------------------------------------- encode ----
__global__ void encode_kernel(const float* __restrict__ x,
                              const float* __restrict__ table,
                              __nv_bfloat16* __restrict__ featb, int N) {
    int i = blockIdx.x * blockDim.x + threadIdx.x;
    if (i >= N) return;

    float x0 = x[3 * i + 0] / 1.5f;
    float x1 = x[3 * i + 1] / 1.5f;
    float x2 = x[3 * i + 2] / 1.5f;

    __nv_bfloat162* f2 = (__nv_bfloat162*)featb;

    #pragma unroll
    for (int l = 0; l < 16; l++) {
        float s = c_scale[l];
        float px = x0 * s + 0.5f;
        float py = x1 * s + 0.5f;
        float pz = x2 * s + 0.5f;
        float fx = floorf(px), fy = floorf(py), fz = floorf(pz);
        float tx = px - fx, ty = py - fy, tz = pz - fz;
        uint32_t X = (uint32_t)fx, Y = (uint32_t)fy, Z = (uint32_t)fz;
        float wx[2] = {1.0f - tx, tx};
        float wy[2] = {1.0f - ty, ty};
        float wz[2] = {1.0f - tz, tz};

        float a0 = 0.0f, a1 = 0.0f;
        #pragma unroll
        for (int c = 0; c < 8; c++) {
            uint32_t bx = (uint32_t)(c & 1);
            uint32_t by = (uint32_t)((c >> 1) & 1);
            uint32_t bz = (uint32_t)((c >> 2) & 1);
            uint32_t cx = X + bx, cy = Y + by, cz = Z + bz;
            uint32_t idx;
            if (l < 5) {
                uint32_t r1 = c_res1[l];
                idx = cx + cy * r1 + cz * r1 * r1;   // dense
            } else {
                idx = (cx * 1u ^ cy * 2654435761u ^ cz * 805459861u) & 524287u;
            }
            float w = wx[bx] * wy[by] * wz[bz];
            float2 t2 = __ldg((const float2*)table + (c_offset[l] + (int)idx));
            a0 += w * t2.x;
            a1 += w * t2.y;
        }
        f2[(size_t)i * 16 + l] = __float22bfloat162_rn(make_float2(a0, a1));
    }
}

// ------------------------------------------------------------ MMA helpers ---
__device__ __forceinline__ uint32_t scvta(const void* p) {
    return (uint32_t)__cvta_generic_to_shared(p);
}
__device__ __forceinline__ void ldsm_x4(uint32_t* r, uint32_t addr) {
    asm volatile("ldmatrix.sync.aligned.m8n8.x4.shared.b16 {%0,%1,%2,%3}, [%4];"
                 : "=r"(r[0]), "=r"(r[1]), "=r"(r[2]), "=r"(r[3]) : "r"(addr));
}
__device__ __forceinline__ void ldsm_x4_t(uint32_t* r, uint32_t addr) {
    asm volatile("ldmatrix.sync.aligned.m8n8.x4.trans.shared.b16 {%0,%1,%2,%3}, [%4];"
                 : "=r"(r[0]), "=r"(r[1]), "=r"(r[2]), "=r"(r[3]) : "r"(addr));
}
__device__ __forceinline__ void mma_bf16(float* c, const uint32_t* a, const uint32_t* b) {
    asm volatile("mma.sync.aligned.m16n8k16.row.col.f32.bf16.bf16.f32 "
                 "{%0,%1,%2,%3}, {%4,%5,%6,%7}, {%8,%9}, {%0,%1,%2,%3};"
                 : "+f"(c[0]), "+f"(c[1]), "+f"(c[2]), "+f"(c[3])
                 : "r"(a[0]), "r"(a[1]), "r"(a[2]), "r"(a[3]),
                   "r"(b[0]), "r"(b[1]));
}

// SMEM layout (elements of bf16): A0 | A1 | W | bias(float)
#define SA  264     // A row stride (bf16), 528 B -> conflict-free ldmatrix
#define SWS 136     // W row stride (bf16), 272 B -> conflict-free ldmatrix
#define A_ELEMS (128 * SA)            // 33792
#define W_ELEMS (256 * SWS)           // 34816
#define SMEM_BYTES ((2 * A_ELEMS + W_ELEMS) * 2 + 128 * 4)   // 205312

// One layer: sOut[128,256] = relu(sIn[128,K] @ W[K,256] + bias), bf16 in/out.
// 8 warps: warp tile 32 rows x 64 cols; 2 column passes of 128.
template <int K>
__device__ __forceinline__ void layer(const __nv_bfloat16* __restrict__ Wg,
                                      const float* __restrict__ bias,
                                      const __nv_bfloat16* sIn,
                                      __nv_bfloat16* sOut,
                                      __nv_bfloat16* sW, float* sBias) {
    const int tid  = threadIdx.x;
    const int lane = tid & 31;
    const int wid  = tid >> 5;
    const int m0   = (wid & 3) * 32;
    const int n0   = (wid >> 2) * 64;
    const int lr   = lane & 15;
    const int lc   = (lane >> 4) << 3;

    #pragma unroll
    for (int pass = 0; pass < 2; pass++) {
        const int colBase = pass * 128;
        __syncthreads();   // sW free / sIn ready
        // load W chunk [K,128] (bf16) + bias[128]
        #pragma unroll
        for (int v = tid; v < K * 16; v += 256) {
            int k = v >> 4, c8 = (v & 15) * 8;
            *(uint4*)(sW + k * SWS + c8) =
                *(const uint4*)(Wg + (size_t)k * 256 + colBase + c8);
        }
        if (tid < 128) sBias[tid] = bias[colBase + tid];
        __syncthreads();

        float acc[2][8][4];
        #pragma unroll
        for (int mi = 0; mi < 2; mi++)
            #pragma unroll
            for (int nj = 0; nj < 8; nj++)
                #pragma unroll
                for (int q = 0; q < 4; q++) acc[mi][nj][q] = 0.0f;

        #pragma unroll
        for (int k0 = 0; k0 < K; k0 += 16) {
            uint32_t afr[2][4];
            #pragma unroll
            for (int mi = 0; mi < 2; mi++)
                ldsm_x4(afr[mi], scvta(sIn + (m0 + mi * 16 + lr) * SA + k0 + lc));
            uint32_t bfr[8][2];
            #pragma unroll
            for (int nq = 0; nq < 4; nq++) {
                uint32_t r[4];
                ldsm_x4_t(r, scvta(sW + (k0 + lr) * SWS + n0 + nq * 16 + lc));
                bfr[nq * 2 + 0][0] = r[0]; bfr[nq * 2 + 0][1] = r[1];
                bfr[nq * 2 + 1][0] = r[2]; bfr[nq * 2 + 1][1] = r[3];
            }
            #pragma unroll
            for (int mi = 0; mi < 2; mi++)
                #pragma unroll
                for (int nj = 0; nj < 8; nj++)
                    mma_bf16(acc[mi][nj], afr[mi], bfr[nj]);
        }

        // bias + relu + store bf16x2
        #pragma unroll
        for (int mi = 0; mi < 2; mi++) {
            #pragma unroll
            for (int nj = 0; nj < 8; nj++) {
                int colL = n0 + nj * 8 + (lane & 3) * 2;
                float b0v = sBias[colL], b1v = sBias[colL + 1];
                int row = m0 + mi * 16 + (lane >> 2);
                float v0 = fmaxf(acc[mi][nj][0] + b0v, 0.0f);
                float v1 = fmaxf(acc[mi][nj][1] + b1v, 0.0f);
                *(__nv_bfloat162*)(sOut + row * SA + colBase + colL) =
                    __float22bfloat162_rn(make_float2(v0, v1));
                float v2 = fmaxf(acc[mi][nj][2] + b0v, 0.0f);
                float v3 = fmaxf(acc[mi][nj][3] + b1v, 0.0f);
                *(__nv_bfloat162*)(sOut + (row + 8) * SA + colBase + colL) =
                    __float22bfloat162_rn(make_float2(v2, v3));
            }
        }
    }
}

// -------------------------------------------------- fully-fused MLP kernel --
__global__ void __launch_bounds__(256, 1)
fused_mlp(const __nv_bfloat16* __restrict__ feat,
          const __nv_bfloat16* __restrict__ w1b,
          const __nv_bfloat16* __restrict__ w2b,
          const __nv_bfloat16* __restrict__ w3b,
          const float* __restrict__ b1, const float* __restrict__ b2,
          const float* __restrict__ b3, const float* __restrict__ w4,
          const float* __restrict__ b4, float* __restrict__ out, int N) {
    extern __shared__ __nv_bfloat16 smem_bf[];
    __nv_bfloat16* sA0 = smem_bf;
    __nv_bfloat16* sA1 = smem_bf + A_ELEMS;
    __nv_bfloat16* sW  = smem_bf + 2 * A_ELEMS;
    float* sBias = (float*)(smem_bf + 2 * A_ELEMS + W_ELEMS);

    const int tid = threadIdx.x;
    const int rowBase = blockIdx.x * 128;

    // load feat tile [128,32] bf16 -> sA0
    #pragma unroll
    for (int v = tid; v < 512; v += 256) {
        int row = v >> 2, j = v & 3;
        int gr = min(rowBase + row, N - 1);
        *(uint4*)(sA0 + row * SA + j * 8) =
            *(const uint4*)(feat + (size_t)gr * 32 + j * 8);
    }

    layer<32>(w1b, b1, sA0, sA1, sW, sBias);
    layer<256>(w2b, b2, sA1, sA0, sW, sBias);
    layer<256>(w3b, b3, sA0, sA1, sW, sBias);

    __syncthreads();
    float* sW4 = (float*)sW;   // 768 w4 + 3 b4
    for (int v = tid; v < 768; v += 256) sW4[v] = w4[v];
    if (tid < 3) sW4[768 + tid] = b4[tid];
    __syncthreads();

    if (tid < 128) {
        int row = tid;
        int gr = rowBase + row;
        float a0 = sW4[768], a1 = sW4[769], a2 = sW4[770];
        const uint4* h4 = (const uint4*)(sA1 + row * SA);
        #pragma unroll
        for (int q = 0; q < 32; q++) {
            uint4 u = h4[q];
            const __nv_bfloat162* p = (const __nv_bfloat162*)&u;
            #pragma unroll
            for (int e = 0; e < 4; e++) {
                float2 hv = __bfloat1622float2(p[e]);
                int k = q * 8 + e * 2;
                a0 += hv.x * sW4[(k + 0) * 3 + 0];
                a1 += hv.x * sW4[(k + 0) * 3 + 1];
                a2 += hv.x * sW4[(k + 0) * 3 + 2];
                a0 += hv.y * sW4[(k + 1) * 3 + 0];
                a1 += hv.y * sW4[(k + 1) * 3 + 1];
                a2 += hv.y * sW4[(k + 1) * 3 + 2];
            }
        }
        if (gr < N) {
            out[3 * gr + 0] = 1.0f / (1.0f + expf(-a0));
            out[3 * gr + 1] = 1.0f / (1.0f + expf(-a1));
            out[3 * gr + 2] = 1.0f / (1.0f + expf(-a2));
        }
    }
}

// --------------------------------------------------------------- launcher ---
extern "C" void kernel_launch(void* const* d_in, const int* in_sizes, int n_in,
                              void* d_out, int out_size) {
    const float* x     = (const float*)d_in[0];
    const float* table = (const float*)d_in[1];
    const float* w1    = (const float*)d_in[2];
    const float* b1    = (const float*)d_in[3];
    const float* w2    = (const float*)d_in[4];
    const float* b2    = (const float*)d_in[5];
    const float* w3    = (const float*)d_in[6];
    const float* b3    = (const float*)d_in[7];
    const float* w4    = (const float*)d_in[8];
    const float* b4    = (const float*)d_in[9];
    float* out = (float*)d_out;

    int N = in_sizes[0] / 3;

    __nv_bfloat16 *featb, *w1b, *w2b, *w3b;
    cudaGetSymbolAddress((void**)&featb, g_featb);
    cudaGetSymbolAddress((void**)&w1b, g_w1b);
    cudaGetSymbolAddress((void**)&w2b, g_w2b);
    cudaGetSymbolAddress((void**)&w3b, g_w3b);

    cudaFuncSetAttribute(fused_mlp, cudaFuncAttributeMaxDynamicSharedMemorySize,
                         SMEM_BYTES);

    cvtw_kernel<<<256, 256>>>(w1, w2, w3, w1b, w2b, w3b);
    encode_kernel<<<(N + 255) / 256, 256>>>(x, table, featb, N);
    fused_mlp<<<(N + 127) / 128, 256, SMEM_BYTES>>>(
        featb, w1b, w2b, w3b, b1, b2, b3, w4, b4, out, N);
}